// round 3
// baseline (speedup 1.0000x reference)
#include <cuda_runtime.h>
#include <math.h>
#include <float.h>

#define NN 100000
#define EE 1600000
#define HH 64
#define CC 10
#define SCAN_BLK 1024
#define SCAN_NBLK ((NN + SCAN_BLK - 1) / SCAN_BLK)   // 98

// ---------------- static device scratch ----------------
__device__ int   g_dst[EE];
__device__ int   g_col[EE];
__device__ int   g_deg[NN];
__device__ int   g_rowptr[NN + 1];
__device__ int   g_cursor[NN];
__device__ int   g_blocksum[SCAN_NBLK];
__device__ float g_h[NN * HH];
__device__ float g_agg[NN * HH];
__device__ int   g_odd_nonzero;

union F2 { float2 f; unsigned long long u; };

__device__ __forceinline__ void ffma2(unsigned long long& d,
                                      unsigned long long a,
                                      unsigned long long b) {
    asm("fma.rn.f32x2 %0, %1, %2, %3;" : "=l"(d) : "l"(a), "l"(b), "l"(d));
}

// ---------------- setup ----------------
__global__ void zero_kernel() {
    int i = blockIdx.x * blockDim.x + threadIdx.x;
    if (i < NN) g_deg[i] = 0;
    if (i == 0) g_odd_nonzero = 0;
}

// int64-vs-int32 edge dtype detection (node ids < 2^31 -> int64 odd words are 0).
__global__ void detect_kernel(const unsigned int* __restrict__ w) {
    int i = blockIdx.x * blockDim.x + threadIdx.x;   // 65536 threads
    unsigned int v = w[2 * i + 1];
    if (v) atomicOr(&g_odd_nonzero, 1);
}

// Extract dst, count in-degrees.
__global__ void convert_kernel(const void* __restrict__ ei) {
    int i = blockIdx.x * blockDim.x + threadIdx.x;
    if (i >= EE) return;
    int d;
    if (g_odd_nonzero == 0) d = (int)((const long long*)ei)[EE + i];
    else                    d = ((const int*)ei)[EE + i];
    g_dst[i] = d;
    atomicAdd(&g_deg[d], 1);
}

// ---------------- multi-block exclusive scan ----------------
__global__ void scan_phase1() {
    __shared__ int warp_sums[32];
    int tid = threadIdx.x;
    int i = blockIdx.x * SCAN_BLK + tid;
    int v = (i < NN) ? g_deg[i] : 0;
    int lane = tid & 31, wid = tid >> 5;

    int incl = v;
#pragma unroll
    for (int off = 1; off < 32; off <<= 1) {
        int t = __shfl_up_sync(0xffffffffu, incl, off);
        if (lane >= off) incl += t;
    }
    if (lane == 31) warp_sums[wid] = incl;
    __syncthreads();
    if (wid == 0) {
        int ws = warp_sums[lane];
        int wincl = ws;
#pragma unroll
        for (int off = 1; off < 32; off <<= 1) {
            int t = __shfl_up_sync(0xffffffffu, wincl, off);
            if (lane >= off) wincl += t;
        }
        warp_sums[lane] = wincl - ws;
        if (lane == 31) g_blocksum[blockIdx.x] = wincl;
    }
    __syncthreads();
    int excl = incl - v + warp_sums[wid];
    if (i < NN) g_rowptr[i] = excl;
}

__global__ void scan_phase2() {
    __shared__ int ws4[4];
    __shared__ int total;
    int tid = threadIdx.x;            // 128 threads
    int v = (tid < SCAN_NBLK) ? g_blocksum[tid] : 0;
    int lane = tid & 31, wid = tid >> 5;
    int incl = v;
#pragma unroll
    for (int off = 1; off < 32; off <<= 1) {
        int t = __shfl_up_sync(0xffffffffu, incl, off);
        if (lane >= off) incl += t;
    }
    if (lane == 31) ws4[wid] = incl;
    __syncthreads();
    if (tid == 0) {
        int c = 0;
        for (int w = 0; w < 4; w++) { int t = ws4[w]; ws4[w] = c; c += t; }
        total = c;
    }
    __syncthreads();
    if (tid < SCAN_NBLK) g_blocksum[tid] = incl - v + ws4[wid];
    if (tid == 0) g_rowptr[NN] = total;
}

__global__ void scan_phase3() {
    int i = blockIdx.x * SCAN_BLK + threadIdx.x;
    if (i >= NN) return;
    int r = g_rowptr[i] + g_blocksum[blockIdx.x];
    g_rowptr[i] = r;
    g_cursor[i] = r;
}

// Scatter src ids into CSR (src read straight from edge_index).
__global__ void scatter_kernel(const void* __restrict__ ei) {
    int i = blockIdx.x * blockDim.x + threadIdx.x;
    if (i >= EE) return;
    int s;
    if (g_odd_nonzero == 0) s = (int)((const long long*)ei)[i];
    else                    s = ((const int*)ei)[i];
    int d = g_dst[i];
    int pos = atomicAdd(&g_cursor[d], 1);
    g_col[pos] = s;
}

// ---------------- segment max: one warp per destination node ----------------
__global__ void segmax_kernel() {
    int gw   = (blockIdx.x * blockDim.x + threadIdx.x) >> 5;
    int lane = threadIdx.x & 31;
    if (gw >= NN) return;
    int beg = g_rowptr[gw], end = g_rowptr[gw + 1];
    float m0 = -FLT_MAX, m1 = -FLT_MAX;
    for (int base = beg; base < end; base += 32) {
        int cnt = min(32, end - base);
        int s = 0;
        if (lane < cnt) s = g_col[base + lane];
        for (int e = 0; e < cnt; e++) {
            int sv = __shfl_sync(0xffffffffu, s, e);
            float2 v = *(const float2*)(g_h + sv * HH + lane * 2);
            m0 = fmaxf(m0, v.x);
            m1 = fmaxf(m1, v.y);
        }
    }
    if (beg == end) { m0 = 0.f; m1 = 0.f; }
    ((float2*)g_agg)[gw * 32 + lane] = make_float2(m0, m1);
}

// ---------------- 64-wide GEMM with packed fp32x2 FMA ----------------
// C = (A [+ A2]) @ W + b.  64 rows x 64 cols per block, 256 threads.
// A staged transposed (Ast[k][m]) so row-pairs load as one LDS.64 broadcast;
// W staged duplicated (Wsd[k][j] = (w,w)) so the broadcast operand is one
// LDS.64 with zero packing ops. Column map j = tx + 16*jj keeps 16 lanes on
// 128B contiguous smem -> conflict-free.
template <bool ADD>
__global__ void gemm64_kernel(const float* __restrict__ A,
                              const float* __restrict__ A2,
                              const float* __restrict__ W,
                              const float* __restrict__ bias,
                              float* __restrict__ Cm, int n) {
    __shared__ float  Ast[64][66];     // [k][m], padded
    __shared__ float2 Wsd[64][64];     // [k][j] duplicated
    int tid = threadIdx.x;
    int block_row = blockIdx.x * 64;

    for (int i = tid; i < 1024; i += 256) {           // W dup
        int k = i >> 4, j4 = i & 15;
        float4 v = ((const float4*)W)[i];
        Wsd[k][j4 * 4 + 0] = make_float2(v.x, v.x);
        Wsd[k][j4 * 4 + 1] = make_float2(v.y, v.y);
        Wsd[k][j4 * 4 + 2] = make_float2(v.z, v.z);
        Wsd[k][j4 * 4 + 3] = make_float2(v.w, v.w);
    }
    for (int i = tid; i < 1024; i += 256) {           // A (+agg) transposed
        int m = i >> 4, k4 = i & 15;
        int row = block_row + m;
        float4 v = make_float4(0.f, 0.f, 0.f, 0.f);
        if (row < n) {
            v = ((const float4*)A)[row * 16 + k4];
            if (ADD) {
                float4 u = ((const float4*)A2)[row * 16 + k4];
                v.x += u.x; v.y += u.y; v.z += u.z; v.w += u.w;
            }
        }
        Ast[k4 * 4 + 0][m] = v.x;
        Ast[k4 * 4 + 1][m] = v.y;
        Ast[k4 * 4 + 2][m] = v.z;
        Ast[k4 * 4 + 3][m] = v.w;
    }
    __syncthreads();

    int tx = tid & 15, ty = tid >> 4;
    int m0 = ty * 4;

    unsigned long long acc01[4] = {0, 0, 0, 0};   // rows m0,m0+1  cols tx+16*jj
    unsigned long long acc23[4] = {0, 0, 0, 0};   // rows m0+2,m0+3

#pragma unroll 16
    for (int k = 0; k < 64; k++) {
        F2 a01, a23, b0, b1, b2, b3;
        a01.f = *(const float2*)&Ast[k][m0];
        a23.f = *(const float2*)&Ast[k][m0 + 2];
        b0.f = Wsd[k][tx];
        b1.f = Wsd[k][tx + 16];
        b2.f = Wsd[k][tx + 32];
        b3.f = Wsd[k][tx + 48];
        ffma2(acc01[0], a01.u, b0.u);
        ffma2(acc01[1], a01.u, b1.u);
        ffma2(acc01[2], a01.u, b2.u);
        ffma2(acc01[3], a01.u, b3.u);
        ffma2(acc23[0], a23.u, b0.u);
        ffma2(acc23[1], a23.u, b1.u);
        ffma2(acc23[2], a23.u, b2.u);
        ffma2(acc23[3], a23.u, b3.u);
    }

#pragma unroll
    for (int jj = 0; jj < 4; jj++) {
        int col = tx + jj * 16;
        float bb = bias[col];
        F2 p01, p23;
        p01.u = acc01[jj];
        p23.u = acc23[jj];
        int r0 = block_row + m0;
        if (r0 + 3 < n) {
            Cm[(r0 + 0) * 64 + col] = p01.f.x + bb;
            Cm[(r0 + 1) * 64 + col] = p01.f.y + bb;
            Cm[(r0 + 2) * 64 + col] = p23.f.x + bb;
            Cm[(r0 + 3) * 64 + col] = p23.f.y + bb;
        } else {
            if (r0 + 0 < n) Cm[(r0 + 0) * 64 + col] = p01.f.x + bb;
            if (r0 + 1 < n) Cm[(r0 + 1) * 64 + col] = p01.f.y + bb;
            if (r0 + 2 < n) Cm[(r0 + 2) * 64 + col] = p23.f.x + bb;
            if (r0 + 3 < n) Cm[(r0 + 3) * 64 + col] = p23.f.y + bb;
        }
    }
}

// ---------------- decoder + log-softmax ----------------
__global__ void decoder_kernel(const float* __restrict__ dw,
                               const float* __restrict__ db,
                               float* __restrict__ out, int n) {
    __shared__ float Ws[HH * CC];
    __shared__ float bs[CC];
    int tid = threadIdx.x;
    for (int i = tid; i < HH * CC; i += blockDim.x) Ws[i] = dw[i];
    if (tid < CC) bs[tid] = db[tid];
    __syncthreads();
    int node = blockIdx.x * blockDim.x + tid;
    if (node >= n) return;
    float acc[CC];
#pragma unroll
    for (int c = 0; c < CC; c++) acc[c] = bs[c];
    const float4* hp = (const float4*)(g_h + node * HH);
#pragma unroll
    for (int k4 = 0; k4 < 16; k4++) {
        float4 v = hp[k4];
        int kb = k4 * 4;
#pragma unroll
        for (int c = 0; c < CC; c++)
            acc[c] += v.x * Ws[(kb + 0) * CC + c] + v.y * Ws[(kb + 1) * CC + c] +
                      v.z * Ws[(kb + 2) * CC + c] + v.w * Ws[(kb + 3) * CC + c];
    }
    float mx = acc[0];
#pragma unroll
    for (int c = 1; c < CC; c++) mx = fmaxf(mx, acc[c]);
    float s = 0.f;
#pragma unroll
    for (int c = 0; c < CC; c++) s += expf(acc[c] - mx);
    float lse = mx + logf(s);
#pragma unroll
    for (int c = 0; c < CC; c++) out[node * CC + c] = acc[c] - lse;
}

// ---------------- launch ----------------
extern "C" void kernel_launch(void* const* d_in, const int* in_sizes, int n_in,
                              void* d_out, int out_size) {
    const float* x      = (const float*)d_in[0];
    const void*  ei     = d_in[1];
    const float* enc_w  = (const float*)d_in[3];
    const float* enc_b  = (const float*)d_in[4];
    const float* proc_w = (const float*)d_in[5];
    const float* proc_b = (const float*)d_in[6];
    const float* dec_w  = (const float*)d_in[7];
    const float* dec_b  = (const float*)d_in[8];
    float* out = (float*)d_out;

    float* hptr = nullptr;
    float* aggptr = nullptr;
    cudaGetSymbolAddress((void**)&hptr, g_h);
    cudaGetSymbolAddress((void**)&aggptr, g_agg);

    const int n = NN;

    // CSR build
    zero_kernel<<<(NN + 255) / 256, 256>>>();
    detect_kernel<<<256, 256>>>((const unsigned int*)ei);
    convert_kernel<<<(EE + 255) / 256, 256>>>(ei);
    scan_phase1<<<SCAN_NBLK, SCAN_BLK>>>();
    scan_phase2<<<1, 128>>>();
    scan_phase3<<<SCAN_NBLK, SCAN_BLK>>>();
    scatter_kernel<<<(EE + 255) / 256, 256>>>(ei);

    // encoder
    gemm64_kernel<false><<<(n + 63) / 64, 256>>>(x, nullptr, enc_w, enc_b, hptr, n);

    // 6 GIN layers
    for (int it = 0; it < 6; it++) {
        segmax_kernel<<<(NN * 32 + 255) / 256, 256>>>();
        gemm64_kernel<true><<<(n + 63) / 64, 256>>>(hptr, aggptr, proc_w, proc_b, hptr, n);
    }

    // decoder + log-softmax
    decoder_kernel<<<(n + 127) / 128, 128>>>(dec_w, dec_b, out, n);
}

// round 4
// speedup vs baseline: 1.1680x; 1.1680x over previous
#include <cuda_runtime.h>
#include <math.h>
#include <float.h>

#define NN 100000
#define EE 1600000
#define HH 64
#define CC 10
#define SCAN_BLK 1024
#define SCAN_NBLK ((NN + SCAN_BLK - 1) / SCAN_BLK)   // 98

#define GT_M 128            // gemm tile rows
#define GT_T 128            // gemm threads
#define GSMEM ((GT_M * 65 + 64 * 66) * 4)   // 50176 bytes

// ---------------- static device scratch ----------------
__device__ int   g_dst[EE];
__device__ int   g_col[EE];
__device__ int   g_deg[NN];
__device__ int   g_rowptr[NN + 1];
__device__ int   g_cursor[NN];
__device__ int   g_blocksum[SCAN_NBLK];
__device__ float g_h[NN * HH];
__device__ float g_agg[NN * HH];
__device__ int   g_odd_nonzero;

union F2 { float2 f; unsigned long long u; };

__device__ __forceinline__ void ffma2(unsigned long long& d,
                                      unsigned long long a,
                                      unsigned long long b) {
    asm("fma.rn.f32x2 %0, %1, %2, %3;" : "=l"(d) : "l"(a), "l"(b), "l"(d));
}
__device__ __forceinline__ unsigned long long dup2(float a) {
    unsigned long long r;
    unsigned int ai = __float_as_uint(a);
    asm("mov.b64 %0, {%1, %1};" : "=l"(r) : "r"(ai));
    return r;
}

// ---------------- setup ----------------
__global__ void zero_kernel() {
    int i = blockIdx.x * blockDim.x + threadIdx.x;
    if (i < NN) g_deg[i] = 0;
    if (i == 0) g_odd_nonzero = 0;
}

// int64-vs-int32 edge dtype detection (node ids < 2^31 -> int64 odd words are 0).
__global__ void detect_kernel(const unsigned int* __restrict__ w) {
    int i = blockIdx.x * blockDim.x + threadIdx.x;   // 65536 threads
    unsigned int v = w[2 * i + 1];
    if (v) atomicOr(&g_odd_nonzero, 1);
}

__global__ void convert_kernel(const void* __restrict__ ei) {
    int i = blockIdx.x * blockDim.x + threadIdx.x;
    if (i >= EE) return;
    int d;
    if (g_odd_nonzero == 0) d = (int)((const long long*)ei)[EE + i];
    else                    d = ((const int*)ei)[EE + i];
    g_dst[i] = d;
    atomicAdd(&g_deg[d], 1);
}

// ---------------- multi-block exclusive scan ----------------
__global__ void scan_phase1() {
    __shared__ int warp_sums[32];
    int tid = threadIdx.x;
    int i = blockIdx.x * SCAN_BLK + tid;
    int v = (i < NN) ? g_deg[i] : 0;
    int lane = tid & 31, wid = tid >> 5;

    int incl = v;
#pragma unroll
    for (int off = 1; off < 32; off <<= 1) {
        int t = __shfl_up_sync(0xffffffffu, incl, off);
        if (lane >= off) incl += t;
    }
    if (lane == 31) warp_sums[wid] = incl;
    __syncthreads();
    if (wid == 0) {
        int ws = warp_sums[lane];
        int wincl = ws;
#pragma unroll
        for (int off = 1; off < 32; off <<= 1) {
            int t = __shfl_up_sync(0xffffffffu, wincl, off);
            if (lane >= off) wincl += t;
        }
        warp_sums[lane] = wincl - ws;
        if (lane == 31) g_blocksum[blockIdx.x] = wincl;
    }
    __syncthreads();
    int excl = incl - v + warp_sums[wid];
    if (i < NN) g_rowptr[i] = excl;
}

__global__ void scan_phase2() {
    __shared__ int ws4[4];
    __shared__ int total;
    int tid = threadIdx.x;            // 128 threads
    int v = (tid < SCAN_NBLK) ? g_blocksum[tid] : 0;
    int lane = tid & 31, wid = tid >> 5;
    int incl = v;
#pragma unroll
    for (int off = 1; off < 32; off <<= 1) {
        int t = __shfl_up_sync(0xffffffffu, incl, off);
        if (lane >= off) incl += t;
    }
    if (lane == 31) ws4[wid] = incl;
    __syncthreads();
    if (tid == 0) {
        int c = 0;
        for (int w = 0; w < 4; w++) { int t = ws4[w]; ws4[w] = c; c += t; }
        total = c;
    }
    __syncthreads();
    if (tid < SCAN_NBLK) g_blocksum[tid] = incl - v + ws4[wid];
    if (tid == 0) g_rowptr[NN] = total;
}

__global__ void scan_phase3() {
    int i = blockIdx.x * SCAN_BLK + threadIdx.x;
    if (i >= NN) return;
    int r = g_rowptr[i] + g_blocksum[blockIdx.x];
    g_rowptr[i] = r;
    g_cursor[i] = r;
}

__global__ void scatter_kernel(const void* __restrict__ ei) {
    int i = blockIdx.x * blockDim.x + threadIdx.x;
    if (i >= EE) return;
    int s;
    if (g_odd_nonzero == 0) s = (int)((const long long*)ei)[i];
    else                    s = ((const int*)ei)[i];
    int d = g_dst[i];
    int pos = atomicAdd(&g_cursor[d], 1);
    g_col[pos] = s;
}

// ---------------- segment max: one warp per destination node ----------------
__global__ void segmax_kernel() {
    int gw   = (blockIdx.x * blockDim.x + threadIdx.x) >> 5;
    int lane = threadIdx.x & 31;
    if (gw >= NN) return;
    int beg = g_rowptr[gw], end = g_rowptr[gw + 1];
    float m0 = -FLT_MAX, m1 = -FLT_MAX;
    for (int base = beg; base < end; base += 32) {
        int cnt = min(32, end - base);
        int s = 0;
        if (lane < cnt) s = g_col[base + lane];
        for (int e = 0; e < cnt; e++) {
            int sv = __shfl_sync(0xffffffffu, s, e);
            float2 v = *(const float2*)(g_h + sv * HH + lane * 2);
            m0 = fmaxf(m0, v.x);
            m1 = fmaxf(m1, v.y);
        }
    }
    if (beg == end) { m0 = 0.f; m1 = 0.f; }
    ((float2*)g_agg)[gw * 32 + lane] = make_float2(m0, m1);
}

// ---------------- 128x64 GEMM, FFMA2, 1B-smem-per-FMA ----------------
// C = (A [+ A2]) @ W + b. 128 threads, 8 rows x 8 cols per thread.
// A row-major in smem with odd stride 65 (conflict-free scalar broadcasts);
// A value duplicated into (a,a) in registers (ALU pipe, not smem BW).
// W stored as natural col-pairs (float2, stride 33 pairs) -> LDS.64, no dup.
template <bool ADD>
__global__ void __launch_bounds__(GT_T, 4)
gemm64x2_kernel(const float* __restrict__ A,
                const float* __restrict__ A2,
                const float* __restrict__ W,
                const float* __restrict__ bias,
                float* __restrict__ Cm, int n) {
    extern __shared__ float smbuf[];
    float*  As  = smbuf;                         // [128][65]
    float2* Ws2 = (float2*)(smbuf + GT_M * 65);  // [64][33] col-pairs

    int tid = threadIdx.x;
    int block_row = blockIdx.x * GT_M;

    // stage W as col-pairs
    for (int i = tid; i < 1024; i += GT_T) {     // 1024 float4s of W
        int k = i >> 4, c4 = i & 15;
        float4 v = ((const float4*)W)[i];
        Ws2[k * 33 + c4 * 2 + 0] = make_float2(v.x, v.y);
        Ws2[k * 33 + c4 * 2 + 1] = make_float2(v.z, v.w);
    }
    // stage A (+A2) rows, row-major stride 65
    for (int i = tid; i < GT_M * 16; i += GT_T) {
        int m = i >> 4, k4 = i & 15;
        int row = block_row + m;
        float4 v = make_float4(0.f, 0.f, 0.f, 0.f);
        if (row < n) {
            v = ((const float4*)A)[row * 16 + k4];
            if (ADD) {
                float4 u = ((const float4*)A2)[row * 16 + k4];
                v.x += u.x; v.y += u.y; v.z += u.z; v.w += u.w;
            }
        }
        float* p = &As[m * 65 + k4 * 4];
        p[0] = v.x; p[1] = v.y; p[2] = v.z; p[3] = v.w;
    }
    __syncthreads();

    int tx = tid & 7;          // 8 thread-cols -> col pairs (2tx+16p, +1)
    int ty = tid >> 3;         // 16 thread-rows -> rows ty*8 .. ty*8+7
    int m0 = ty * 8;

    unsigned long long acc[8][4];
#pragma unroll
    for (int r = 0; r < 8; r++)
#pragma unroll
        for (int p = 0; p < 4; p++) acc[r][p] = 0ull;

#pragma unroll 8
    for (int k = 0; k < 64; k++) {
        F2 b0, b1, b2, b3;
        b0.f = Ws2[k * 33 + tx];
        b1.f = Ws2[k * 33 + tx + 8];
        b2.f = Ws2[k * 33 + tx + 16];
        b3.f = Ws2[k * 33 + tx + 24];
        const float* arow = &As[m0 * 65 + k];
#pragma unroll
        for (int r = 0; r < 8; r++) {
            unsigned long long ad = dup2(arow[r * 65]);
            ffma2(acc[r][0], ad, b0.u);
            ffma2(acc[r][1], ad, b1.u);
            ffma2(acc[r][2], ad, b2.u);
            ffma2(acc[r][3], ad, b3.u);
        }
    }

#pragma unroll
    for (int p = 0; p < 4; p++) {
        int c = 2 * tx + 16 * p;
        float2 bb = *(const float2*)&bias[c];
#pragma unroll
        for (int r = 0; r < 8; r++) {
            int row = block_row + m0 + r;
            if (row < n) {
                F2 v; v.u = acc[r][p];
                *(float2*)&Cm[row * 64 + c] = make_float2(v.f.x + bb.x, v.f.y + bb.y);
            }
        }
    }
}

// ---------------- decoder + log-softmax ----------------
__global__ void decoder_kernel(const float* __restrict__ dw,
                               const float* __restrict__ db,
                               float* __restrict__ out, int n) {
    __shared__ float Ws[HH * CC];
    __shared__ float bs[CC];
    int tid = threadIdx.x;
    for (int i = tid; i < HH * CC; i += blockDim.x) Ws[i] = dw[i];
    if (tid < CC) bs[tid] = db[tid];
    __syncthreads();
    int node = blockIdx.x * blockDim.x + tid;
    if (node >= n) return;
    float acc[CC];
#pragma unroll
    for (int c = 0; c < CC; c++) acc[c] = bs[c];
    const float4* hp = (const float4*)(g_h + node * HH);
#pragma unroll
    for (int k4 = 0; k4 < 16; k4++) {
        float4 v = hp[k4];
        int kb = k4 * 4;
#pragma unroll
        for (int c = 0; c < CC; c++)
            acc[c] += v.x * Ws[(kb + 0) * CC + c] + v.y * Ws[(kb + 1) * CC + c] +
                      v.z * Ws[(kb + 2) * CC + c] + v.w * Ws[(kb + 3) * CC + c];
    }
    float mx = acc[0];
#pragma unroll
    for (int c = 1; c < CC; c++) mx = fmaxf(mx, acc[c]);
    float s = 0.f;
#pragma unroll
    for (int c = 0; c < CC; c++) s += expf(acc[c] - mx);
    float lse = mx + logf(s);
#pragma unroll
    for (int c = 0; c < CC; c++) out[node * CC + c] = acc[c] - lse;
}

// ---------------- launch ----------------
extern "C" void kernel_launch(void* const* d_in, const int* in_sizes, int n_in,
                              void* d_out, int out_size) {
    const float* x      = (const float*)d_in[0];
    const void*  ei     = d_in[1];
    const float* enc_w  = (const float*)d_in[3];
    const float* enc_b  = (const float*)d_in[4];
    const float* proc_w = (const float*)d_in[5];
    const float* proc_b = (const float*)d_in[6];
    const float* dec_w  = (const float*)d_in[7];
    const float* dec_b  = (const float*)d_in[8];
    float* out = (float*)d_out;

    float* hptr = nullptr;
    float* aggptr = nullptr;
    cudaGetSymbolAddress((void**)&hptr, g_h);
    cudaGetSymbolAddress((void**)&aggptr, g_agg);

    cudaFuncSetAttribute(gemm64x2_kernel<false>,
                         cudaFuncAttributeMaxDynamicSharedMemorySize, GSMEM);
    cudaFuncSetAttribute(gemm64x2_kernel<true>,
                         cudaFuncAttributeMaxDynamicSharedMemorySize, GSMEM);

    const int n = NN;
    const int ggrid = (n + GT_M - 1) / GT_M;

    // CSR build
    zero_kernel<<<(NN + 255) / 256, 256>>>();
    detect_kernel<<<256, 256>>>((const unsigned int*)ei);
    convert_kernel<<<(EE + 255) / 256, 256>>>(ei);
    scan_phase1<<<SCAN_NBLK, SCAN_BLK>>>();
    scan_phase2<<<1, 128>>>();
    scan_phase3<<<SCAN_NBLK, SCAN_BLK>>>();
    scatter_kernel<<<(EE + 255) / 256, 256>>>(ei);

    // encoder
    gemm64x2_kernel<false><<<ggrid, GT_T, GSMEM>>>(x, nullptr, enc_w, enc_b, hptr, n);

    // 6 GIN layers
    for (int it = 0; it < 6; it++) {
        segmax_kernel<<<(NN * 32 + 255) / 256, 256>>>();
        gemm64x2_kernel<true><<<ggrid, GT_T, GSMEM>>>(hptr, aggptr, proc_w, proc_b, hptr, n);
    }

    // decoder + log-softmax
    decoder_kernel<<<(n + 127) / 128, 128>>>(dec_w, dec_b, out, n);
}